// round 2
// baseline (speedup 1.0000x reference)
#include <cuda_runtime.h>
#include <stdint.h>

// Problem constants (fixed by setup_inputs / init_kwargs)
#define LSEQ  2048
#define DDIM  64
#define KMAX  64
#define MAXB  16   // generous upper bound on batch for static scratch

// Packed binary codes: group0 = bits 0..31, group1 = bits 32..63.
// Static __device__ scratch (no allocation allowed).
__device__ uint32_t g_qlo[MAXB * LSEQ];
__device__ uint32_t g_qhi[MAXB * LSEQ];
__device__ uint32_t g_klo[MAXB * LSEQ];
__device__ uint32_t g_khi[MAXB * LSEQ];

// Kernel 1: binary-quantize and pack. One warp per token per tensor.
// Lane d reads dims d and d+32; two ballots give the two 32-bit group codes.
__global__ void pack_codes_kernel(const float* __restrict__ q,
                                  const float* __restrict__ k,
                                  int ntok) {
    int w    = (blockIdx.x * blockDim.x + threadIdx.x) >> 5;
    int lane = threadIdx.x & 31;
    if (w >= 2 * ntok) return;
    bool is_q = (w < ntok);
    int  t    = is_q ? w : (w - ntok);
    const float* src = is_q ? q : k;

    float a = src[(size_t)t * DDIM + lane];
    float b = src[(size_t)t * DDIM + lane + 32];
    uint32_t lo = __ballot_sync(0xFFFFFFFFu, a > 0.0f);
    uint32_t hi = __ballot_sync(0xFFFFFFFFu, b > 0.0f);
    if (lane == 0) {
        if (is_q) { g_qlo[t] = lo; g_qhi[t] = hi; }
        else      { g_klo[t] = lo; g_khi[t] = hi; }
    }
}

// Kernel 2: per-query candidate scan. Block = 8 warps = 8 queries of one
// batch; keys of the batch live in smem (16 KB). Each warp scans 32 keys
// per iteration, ballots matches, and serializes indices in ascending
// order via prefix popcount. Output (float32!) pre-filled with -1.0f.
__global__ void __launch_bounds__(256)
match_kernel(float* __restrict__ out) {
    __shared__ uint32_t sklo[LSEQ];
    __shared__ uint32_t skhi[LSEQ];

    const int b   = blockIdx.y;
    const int tid = threadIdx.x;

    // Cooperative load of this batch's packed keys.
    #pragma unroll
    for (int i = 0; i < LSEQ / 256; i++) {
        int idx = i * 256 + tid;
        sklo[idx] = g_klo[b * LSEQ + idx];
        skhi[idx] = g_khi[b * LSEQ + idx];
    }
    __syncthreads();

    const int warp = tid >> 5;
    const int lane = tid & 31;
    const int q    = blockIdx.x * 8 + warp;

    const uint32_t qlo = g_qlo[b * LSEQ + q];
    const uint32_t qhi = g_qhi[b * LSEQ + q];

    float* o = out + ((size_t)b * LSEQ + q) * KMAX;
    // Pre-fill with -1.0f (64 slots, 2 per lane).
    o[lane]      = -1.0f;
    o[lane + 32] = -1.0f;

    const uint32_t ltmask = (1u << lane) - 1u;
    int count = 0;

    #pragma unroll 4
    for (int c = 0; c < LSEQ / 32; c++) {
        int j = c * 32 + lane;
        bool m = (sklo[j] == qlo) || (skhi[j] == qhi);
        uint32_t mask = __ballot_sync(0xFFFFFFFFu, m);
        if (mask) {
            int pos = count + __popc(mask & ltmask);
            if (m && pos < KMAX) o[pos] = (float)j;
            count += __popc(mask);
            if (count >= KMAX) break;   // first KMAX (ascending) already written
        }
    }
}

extern "C" void kernel_launch(void* const* d_in, const int* in_sizes, int n_in,
                              void* d_out, int out_size) {
    const float* q = (const float*)d_in[0];
    const float* k = (const float*)d_in[1];
    // d_in[2] = head_idx, unused by the reference computation.

    int B = out_size / (LSEQ * KMAX);   // out is [B, L, KMAX]
    if (B < 1) B = 1;
    if (B > MAXB) B = MAXB;
    int ntok = B * LSEQ;

    // Pack: 2*ntok warps total.
    int total_threads = 2 * ntok * 32;
    int threads = 256;
    int blocks  = (total_threads + threads - 1) / threads;
    pack_codes_kernel<<<blocks, threads>>>(q, k, ntok);

    // Match: 8 queries per block.
    dim3 grid(LSEQ / 8, B);
    match_kernel<<<grid, 256>>>((float*)d_out);
}

// round 3
// speedup vs baseline: 1.1825x; 1.1825x over previous
#include <cuda_runtime.h>
#include <stdint.h>

#define LSEQ  2048
#define DDIM  64
#define KMAX  64
#define MAXB  16

// Packed key codes (group0 = dims 0..31, group1 = dims 32..63).
__device__ uint32_t g_klo[MAXB * LSEQ];
__device__ uint32_t g_khi[MAXB * LSEQ];

// Kernel 1: pack keys only. One warp per key token.
__global__ void pack_keys_kernel(const float* __restrict__ k, int ntok) {
    int w    = (blockIdx.x * blockDim.x + threadIdx.x) >> 5;
    int lane = threadIdx.x & 31;
    if (w >= ntok) return;
    float a = k[(size_t)w * DDIM + lane];
    float b = k[(size_t)w * DDIM + lane + 32];
    uint32_t lo = __ballot_sync(0xFFFFFFFFu, a > 0.0f);
    uint32_t hi = __ballot_sync(0xFFFFFFFFu, b > 0.0f);
    if (lane == 0) { g_klo[w] = lo; g_khi[w] = hi; }
}

// Kernel 2: 128 threads = 4 warps; each warp handles 4 queries, packing its
// own query codes via ballot. Keys (packed) in smem; each lane tests 2 keys
// per iteration (LDS.64). Fast path: one folded ballot per query per 64 keys.
// Slow path (rare collisions): exact ascending positions via 2 ballots +
// prefix popcount over the even/odd interleave.
__global__ void __launch_bounds__(128)
match_kernel(const float* __restrict__ q, float* __restrict__ out) {
    __shared__ uint32_t sklo[LSEQ];
    __shared__ uint32_t skhi[LSEQ];

    const int b   = blockIdx.y;
    const int tid = threadIdx.x;
    const int warp = tid >> 5;
    const int lane = tid & 31;

    // Cooperative vectorized load of this batch's packed keys (16 KB).
    {
        const uint4* glo = (const uint4*)(g_klo + b * LSEQ);
        const uint4* ghi = (const uint4*)(g_khi + b * LSEQ);
        uint4* slo4 = (uint4*)sklo;
        uint4* shi4 = (uint4*)skhi;
        #pragma unroll
        for (int i = 0; i < LSEQ / 4 / 128; i++) {   // 4 iters
            slo4[i * 128 + tid] = glo[i * 128 + tid];
            shi4[i * 128 + tid] = ghi[i * 128 + tid];
        }
    }

    // This warp's 4 queries: pack codes from fp32 directly (overlaps TMA-less
    // smem fill above; ballots are warp-local, no syncthreads needed yet).
    const int q0 = blockIdx.x * 16 + warp * 4;
    uint32_t qlo[4], qhi[4];
    #pragma unroll
    for (int i = 0; i < 4; i++) {
        const float* qp = q + ((size_t)b * LSEQ + q0 + i) * DDIM;
        float a = qp[lane];
        float c = qp[lane + 32];
        qlo[i] = __ballot_sync(0xFFFFFFFFu, a > 0.0f);
        qhi[i] = __ballot_sync(0xFFFFFFFFu, c > 0.0f);
    }

    // Pre-fill output with -1.0f (fp32 output per harness dtype).
    #pragma unroll
    for (int i = 0; i < 4; i++) {
        float* o = out + ((size_t)b * LSEQ + q0 + i) * KMAX;
        o[lane]      = -1.0f;
        o[lane + 32] = -1.0f;
    }

    __syncthreads();

    int count[4] = {0, 0, 0, 0};
    const uint32_t ltmask = (1u << lane) - 1u;
    const uint2* slo2 = (const uint2*)sklo;
    const uint2* shi2 = (const uint2*)skhi;

    for (int c = 0; c < LSEQ / 64; c++) {            // 32 iterations
        const uint2 kl = slo2[c * 32 + lane];        // keys base+2*lane, +1
        const uint2 kh = shi2[c * 32 + lane];
        const int base = c * 64;
        #pragma unroll
        for (int i = 0; i < 4; i++) {
            // Folded any-match predicate for this lane's 2 keys vs query i.
            bool anym = (kl.x == qlo[i]) | (kh.x == qhi[i]) |
                        (kl.y == qlo[i]) | (kh.y == qhi[i]);
            uint32_t am = __ballot_sync(0xFFFFFFFFu, anym);
            if (am) {   // warp-uniform, rare
                bool m0 = (kl.x == qlo[i]) | (kh.x == qhi[i]);
                bool m1 = (kl.y == qlo[i]) | (kh.y == qhi[i]);
                uint32_t mask0 = __ballot_sync(0xFFFFFFFFu, m0);
                uint32_t mask1 = __ballot_sync(0xFFFFFFFFu, m1);
                float* o = out + ((size_t)b * LSEQ + q0 + i) * KMAX;
                if (m0) {   // key j = base + 2*lane
                    int pos = count[i] + __popc(mask0 & ltmask)
                                       + __popc(mask1 & ltmask);
                    if (pos < KMAX) o[pos] = (float)(base + 2 * lane);
                }
                if (m1) {   // key j = base + 2*lane + 1
                    int pos = count[i] + __popc(mask0 & (ltmask | (1u << lane)))
                                       + __popc(mask1 & ltmask);
                    if (pos < KMAX) o[pos] = (float)(base + 2 * lane + 1);
                }
                count[i] += __popc(mask0) + __popc(mask1);
            }
        }
    }
}

extern "C" void kernel_launch(void* const* d_in, const int* in_sizes, int n_in,
                              void* d_out, int out_size) {
    const float* q = (const float*)d_in[0];
    const float* k = (const float*)d_in[1];

    int B = out_size / (LSEQ * KMAX);   // out is [B, L, KMAX]
    if (B < 1) B = 1;
    if (B > MAXB) B = MAXB;
    int ntok = B * LSEQ;

    // Pack keys: ntok warps.
    int threads = 256;
    int blocks  = (ntok * 32 + threads - 1) / threads;
    pack_keys_kernel<<<blocks, threads>>>(k, ntok);

    // Match: 16 queries per 128-thread block.
    dim3 grid(LSEQ / 16, B);
    match_kernel<<<grid, 128>>>(q, (float*)d_out);
}